// round 2
// baseline (speedup 1.0000x reference)
#include <cuda_runtime.h>
#include <cstdint>

#define N_PAT 8192
#define N_BITS 4096

// U[i][r] = 4 if W[r][i] == state[i] else 0  ->  h_new[r] = h[r] + 2 - U[i][r]
// (u = 2*v_i*W[r][i] in {-2,+2}; h_new = h - u = h + 2 - 4*[W==v])
__device__ unsigned char g_U[(size_t)N_BITS * N_PAT];  // 32 MB scratch
__device__ int g_h0[N_PAT];

// ---------------------------------------------------------------------------
// Prep 1: build U (tiled "transpose" of W with the sign-match applied).
// Tile: 32 i-columns x 128 r-rows. Block (32,8). Grid (4096/32, 8192/128).
// ---------------------------------------------------------------------------
__global__ void k_buildU(const float* __restrict__ W, const float* __restrict__ state) {
    __shared__ unsigned char sm[32][132];   // [i_local][r_local], padded
    int i0 = blockIdx.x * 32;
    int r0 = blockIdx.y * 128;
    int tx = threadIdx.x, ty = threadIdx.y;
    float v = state[i0 + tx];
    #pragma unroll
    for (int j = 0; j < 16; j++) {
        int r = r0 + ty + j * 8;
        float w = W[(size_t)r * N_BITS + i0 + tx];      // coalesced along i
        sm[tx][ty + j * 8] = (w == v) ? (unsigned char)4 : (unsigned char)0;
    }
    __syncthreads();
    #pragma unroll
    for (int jj = 0; jj < 4; jj++) {
        int il = ty + jj * 8;
        uchar4 val;
        val.x = sm[il][4 * tx + 0];
        val.y = sm[il][4 * tx + 1];
        val.z = sm[il][4 * tx + 2];
        val.w = sm[il][4 * tx + 3];
        *reinterpret_cast<uchar4*>(&g_U[(size_t)(i0 + il) * N_PAT + r0 + 4 * tx]) = val;  // coalesced along r
    }
}

// ---------------------------------------------------------------------------
// Prep 2: h0 = W @ state (one warp per row; exact: h integral, |h| <= 4096),
// and initialize out = state (out buffer is poisoned by the harness).
// ---------------------------------------------------------------------------
__global__ void k_h0(const float* __restrict__ W, const float* __restrict__ state,
                     float* __restrict__ out) {
    int gid = blockIdx.x * blockDim.x + threadIdx.x;
    if (gid < N_BITS) out[gid] = state[gid];
    int warp = gid >> 5;
    int lane = threadIdx.x & 31;
    if (warp >= N_PAT) return;
    const float* row = W + (size_t)warp * N_BITS;
    float acc = 0.f;
    #pragma unroll 4
    for (int i = lane; i < N_BITS; i += 32) acc += row[i] * state[i];
    #pragma unroll
    for (int off = 16; off; off >>= 1) acc += __shfl_xor_sync(0xffffffffu, acc, off);
    if (lane == 0) g_h0[warp] = __float2int_rn(acc);
}

// ---------------------------------------------------------------------------
// Main: single persistent CTA, 1024 threads, 8 rows (h values) per thread.
// Per step: h_new[r] = h[r] + 2 - U[i][r]; accept iff the exact int32
// sum(relu(h_new)^2) - sum(relu(h)^2) > 0 (energy strictly decreases).
// Per-step reduced quantity is the DELTA (|delta| <= 8192*(4*4096+4) < 2^27),
// so redux.sync.s32 over warp / 32 partials cannot overflow.
// One __syncthreads per step (double-buffered warp partials, every warp
// redundantly reduces the 32 partials so no second barrier is needed).
// Next column is prefetched from L2 one step ahead.
// ---------------------------------------------------------------------------
__global__ __launch_bounds__(1024, 1)
void k_main(const float* __restrict__ state, const int* __restrict__ perm,
            float* __restrict__ out) {
    __shared__ float s_state[N_BITS];
    __shared__ int   s_perm[N_BITS];
    __shared__ int   s_wpart[2][32];

    int t = threadIdx.x;
    for (int k = t; k < N_BITS; k += 1024) {
        s_state[k] = state[k];
        s_perm[k]  = perm[k];
    }

    const unsigned char* __restrict__ Ubase = g_U + t * 8;  // column offset folded once

    int h[8];
    #pragma unroll
    for (int k = 0; k < 8; k++) h[k] = g_h0[t * 8 + k];
    int P = 0;
    #pragma unroll
    for (int k = 0; k < 8; k++) { int m = max(h[k], 0); P += m * m; }

    __syncthreads();

    int ip  = s_perm[0];
    int ipn = s_perm[1];
    uint2 uc = __ldg(reinterpret_cast<const uint2*>(Ubase + (unsigned)ip * N_PAT));

    #pragma unroll 1
    for (int s = 0; s < N_BITS; s++) {
        // prefetch next step's column + next-next perm index (clamped)
        uint2 un = __ldg(reinterpret_cast<const uint2*>(Ubase + (unsigned)ipn * N_PAT));
        int ipnn = s_perm[(s + 2 < N_BITS) ? (s + 2) : (N_BITS - 1)];

        int hn[8];
        int Pn = 0;
        unsigned lo = uc.x, hi = uc.y;
        #pragma unroll
        for (int k = 0; k < 4; k++) {
            int e  = __byte_perm(lo, 0, 0x4440 + k);   // byte k, zero-extended
            int v2 = h[k] + 2 - e;
            hn[k]  = v2;
            int m  = max(v2, 0);
            Pn += m * m;
        }
        #pragma unroll
        for (int k = 0; k < 4; k++) {
            int e  = __byte_perm(hi, 0, 0x4440 + k);
            int v2 = h[4 + k] + 2 - e;
            hn[4 + k] = v2;
            int m  = max(v2, 0);
            Pn += m * m;
        }

        int d = Pn - P;
        int wred = __reduce_add_sync(0xffffffffu, d);          // warp partial of delta
        if ((t & 31) == 0) s_wpart[s & 1][t >> 5] = wred;
        __syncthreads();
        int total = __reduce_add_sync(0xffffffffu, s_wpart[s & 1][t & 31]);

        if (total > 0) {   // energy strictly decreases -> accept flip
            P = Pn;
            #pragma unroll
            for (int k = 0; k < 8; k++) h[k] = hn[k];
            if (t == 0) out[ip] = -s_state[ip];
        }

        ip = ipn; ipn = ipnn; uc = un;
    }
}

// ---------------------------------------------------------------------------
extern "C" void kernel_launch(void* const* d_in, const int* in_sizes, int n_in,
                              void* d_out, int out_size) {
    const float* W     = (const float*)d_in[0];
    const float* state = (const float*)d_in[1];
    const int*   perm  = (const int*)d_in[2];
    float*       out   = (float*)d_out;

    dim3 b1(32, 8), g1(N_BITS / 32, N_PAT / 128);
    k_buildU<<<g1, b1>>>(W, state);
    k_h0<<<(N_PAT * 32) / 256, 256>>>(W, state, out);
    k_main<<<1, 1024>>>(state, perm, out);
}

// round 3
// speedup vs baseline: 1.0884x; 1.0884x over previous
#include <cuda_runtime.h>
#include <cstdint>

#define N_PAT 8192
#define N_BITS 4096

// c[i][r] = 2 - 4*[W[r][i]==state[i]]  in {+2,-2}, stored as s16.
// h_new[r] = h[r] + c[i][r]   (exactly the reference's  h - 2*v_i*W[:,i])
__device__ short g_U16[(size_t)N_BITS * N_PAT];  // 64 MB scratch
__device__ int   g_h0[N_PAT];

// ---------------------------------------------------------------------------
// Prep 1: build c table (tiled transpose of W with sign-match applied).
// Tile: 32 i-columns x 128 r-rows. Block (32,8). Grid (4096/32, 8192/128).
// ---------------------------------------------------------------------------
__global__ void k_buildU(const float* __restrict__ W, const float* __restrict__ state) {
    __shared__ unsigned char sm[32][132];   // [i_local][r_local] match flags, padded
    int i0 = blockIdx.x * 32;
    int r0 = blockIdx.y * 128;
    int tx = threadIdx.x, ty = threadIdx.y;
    float v = state[i0 + tx];
    #pragma unroll
    for (int j = 0; j < 16; j++) {
        float w = W[(size_t)(r0 + ty + j * 8) * N_BITS + i0 + tx];   // coalesced along i
        sm[tx][ty + j * 8] = (w == v) ? 1 : 0;
    }
    __syncthreads();
    #pragma unroll
    for (int jj = 0; jj < 4; jj++) {
        int il = ty + jj * 8;
        short4 val;
        val.x = (short)(2 - 4 * (int)sm[il][4 * tx + 0]);
        val.y = (short)(2 - 4 * (int)sm[il][4 * tx + 1]);
        val.z = (short)(2 - 4 * (int)sm[il][4 * tx + 2]);
        val.w = (short)(2 - 4 * (int)sm[il][4 * tx + 3]);
        *reinterpret_cast<short4*>(&g_U16[(size_t)(i0 + il) * N_PAT + r0 + 4 * tx]) = val;
    }
}

// ---------------------------------------------------------------------------
// Prep 2: h0 from the table itself: W[r][i]*state[i] = -c[i][r]/2, so
// h0[r] = -(sum_i c[i][r]) / 2. One thread per PAIR of rows, packed s16
// accumulation (|sum per lane| <= 8192 fits s16). Fully coalesced 64 MB read.
// Also initializes out = state (out is poisoned by the harness).
// ---------------------------------------------------------------------------
__global__ void k_h0t(const float* __restrict__ state, float* __restrict__ out) {
    int t = blockIdx.x * blockDim.x + threadIdx.x;   // 0..4095
    out[t] = state[t];
    const int* col = reinterpret_cast<const int*>(g_U16) + t;   // row-pair t, stride N_PAT/2 ints
    int acc2 = 0;
    #pragma unroll 8
    for (int i = 0; i < N_BITS; i++)
        acc2 = __vadd2(acc2, col[(size_t)i * (N_PAT / 2)]);
    int lo = (int)(short)(acc2 & 0xFFFF);   // signed s16 lane sums (always even)
    int hi = acc2 >> 16;                    // arithmetic shift
    g_h0[2 * t]     = -(lo >> 1);
    g_h0[2 * t + 1] = -(hi >> 1);
}

// ---------------------------------------------------------------------------
// Main: single persistent CTA, 512 threads, 16 rows per thread held as 8
// packed s16x2 registers. Per 2 elements: VADD2 + VMAXS2 (+2 unpack, 2 IMAD)
// -> 2 alu + 1 fma ops/element (was 3 alu + 1 fma). Accept iff exact int32
// sum(relu(h_new)^2) - sum(relu(h)^2) > 0. One __syncthreads per step
// (double-buffered warp partials; every warp redundantly reduces so no 2nd
// barrier). Next column (two uint4) prefetched from L2 one step ahead.
// ---------------------------------------------------------------------------
__global__ __launch_bounds__(512, 1)
void k_main(const float* __restrict__ state, const int* __restrict__ perm,
            float* __restrict__ out) {
    __shared__ float s_state[N_BITS];
    __shared__ int   s_perm[N_BITS];
    __shared__ int   s_wpart[2][32];

    int t = threadIdx.x;
    for (int k = t; k < N_BITS; k += 512) {
        s_state[k] = state[k];
        s_perm[k]  = perm[k];
    }
    if (t < 32) { s_wpart[0][t] = 0; s_wpart[1][t] = 0; }   // warps 16..31 don't exist

    const short* __restrict__ Ub = g_U16 + t * 16;   // this thread's 16-row slice

    int h2[8];
    int P = 0;
    #pragma unroll
    for (int k = 0; k < 8; k++) {
        int a = g_h0[t * 16 + 2 * k];
        int b = g_h0[t * 16 + 2 * k + 1];
        h2[k] = (a & 0xFFFF) | (b << 16);
        int ma = max(a, 0), mb = max(b, 0);
        P += ma * ma + mb * mb;
    }
    __syncthreads();

    int ip  = s_perm[0];
    int ipn = s_perm[1];
    uint4 cA = __ldg(reinterpret_cast<const uint4*>(Ub + (size_t)ip * N_PAT));
    uint4 cB = __ldg(reinterpret_cast<const uint4*>(Ub + (size_t)ip * N_PAT + 8));

    #pragma unroll 1
    for (int s = 0; s < N_BITS; s++) {
        // prefetch next step's column + next-next perm index (clamped)
        uint4 nA = __ldg(reinterpret_cast<const uint4*>(Ub + (size_t)ipn * N_PAT));
        uint4 nB = __ldg(reinterpret_cast<const uint4*>(Ub + (size_t)ipn * N_PAT + 8));
        int ipnn = s_perm[(s + 2 < N_BITS) ? (s + 2) : (N_BITS - 1)];

        int hn2[8];
        int Pa = 0, Pb = 0;   // two accumulator chains

#define BODY(idx, cword, ACC) {                           \
        int hn = __vadd2(h2[idx], (int)(cword));          \
        hn2[idx] = hn;                                    \
        unsigned mn = __vmaxs2((unsigned)hn, 0u);         \
        int lo = (int)(mn & 0xFFFFu);                     \
        int hi = (int)(mn >> 16);                         \
        ACC += lo * lo;                                   \
        ACC += hi * hi; }

        BODY(0, cA.x, Pa) BODY(1, cA.y, Pb)
        BODY(2, cA.z, Pa) BODY(3, cA.w, Pb)
        BODY(4, cB.x, Pa) BODY(5, cB.y, Pb)
        BODY(6, cB.z, Pa) BODY(7, cB.w, Pb)
#undef BODY

        int Pn = Pa + Pb;
        int d  = Pn - P;                                       // |d| < 2^19 per thread
        int wr = __reduce_add_sync(0xffffffffu, d);            // warp partial of delta
        if ((t & 31) == 0) s_wpart[s & 1][t >> 5] = wr;
        __syncthreads();
        // every warp redundantly reduces the 32 partials (16 live, 16 zero)
        int total = __reduce_add_sync(0xffffffffu, s_wpart[s & 1][t & 31]);

        if (total > 0) {   // energy strictly decreases -> accept flip
            P = Pn;
            #pragma unroll
            for (int k = 0; k < 8; k++) h2[k] = hn2[k];
            if (t == 0) out[ip] = -s_state[ip];
        }

        ip = ipn; ipn = ipnn; cA = nA; cB = nB;
    }
}

// ---------------------------------------------------------------------------
extern "C" void kernel_launch(void* const* d_in, const int* in_sizes, int n_in,
                              void* d_out, int out_size) {
    const float* W     = (const float*)d_in[0];
    const float* state = (const float*)d_in[1];
    const int*   perm  = (const int*)d_in[2];
    float*       out   = (float*)d_out;

    dim3 b1(32, 8), g1(N_BITS / 32, N_PAT / 128);
    k_buildU<<<g1, b1>>>(W, state);
    k_h0t<<<N_BITS / 256, 256>>>(state, out);
    k_main<<<1, 512>>>(state, perm, out);
}

// round 4
// speedup vs baseline: 1.1203x; 1.0293x over previous
#include <cuda_runtime.h>
#include <cstdint>

#define N_PAT 8192
#define N_BITS 4096

// c'[i][r] = -state[i]*W[r][i] in {+1,-1}, stored s16.
// Halved domain: g = h/2; flip i => g_new = g + c'[i].  (h stays even.)
__device__ short g_C[(size_t)N_BITS * N_PAT];  // 64 MB scratch
__device__ int   g_g0[N_PAT];

// ---------------------------------------------------------------------------
// Prep 1: build c' table (tiled transpose of W with sign-match applied).
// ---------------------------------------------------------------------------
__global__ void k_buildU(const float* __restrict__ W, const float* __restrict__ state) {
    __shared__ unsigned char sm[32][132];   // match flags, padded
    int i0 = blockIdx.x * 32;
    int r0 = blockIdx.y * 128;
    int tx = threadIdx.x, ty = threadIdx.y;
    float v = state[i0 + tx];
    #pragma unroll
    for (int j = 0; j < 16; j++) {
        float w = W[(size_t)(r0 + ty + j * 8) * N_BITS + i0 + tx];   // coalesced along i
        sm[tx][ty + j * 8] = (w == v) ? 1 : 0;
    }
    __syncthreads();
    #pragma unroll
    for (int jj = 0; jj < 4; jj++) {
        int il = ty + jj * 8;
        short4 val;                                   // match -> -1, mismatch -> +1
        val.x = (short)(1 - 2 * (int)sm[il][4 * tx + 0]);
        val.y = (short)(1 - 2 * (int)sm[il][4 * tx + 1]);
        val.z = (short)(1 - 2 * (int)sm[il][4 * tx + 2]);
        val.w = (short)(1 - 2 * (int)sm[il][4 * tx + 3]);
        *reinterpret_cast<short4*>(&g_C[(size_t)(i0 + il) * N_PAT + r0 + 4 * tx]) = val;
    }
}

// ---------------------------------------------------------------------------
// Prep 2: g0[r] = (W @ state)[r] / 2 = -(sum_i c'[i][r]) / 2, from the table
// itself (coalesced 64 MB read; leaves table L2-hot). Packed s16 accumulation
// (|lane sum| <= 4096, even). Also out = state (out is poisoned).
// ---------------------------------------------------------------------------
__global__ void k_h0t(const float* __restrict__ state, float* __restrict__ out) {
    int t = blockIdx.x * blockDim.x + threadIdx.x;   // 0..4095 (row pair)
    out[t] = state[t];
    const int* col = reinterpret_cast<const int*>(g_C) + t;
    int acc2 = 0;
    #pragma unroll 8
    for (int i = 0; i < N_BITS; i++)
        acc2 = __vadd2(acc2, col[(size_t)i * (N_PAT / 2)]);
    int lo = (int)(short)(acc2 & 0xFFFF);
    int hi = acc2 >> 16;
    g_g0[2 * t]     = -(lo >> 1);
    g_g0[2 * t + 1] = -(hi >> 1);
}

// ---------------------------------------------------------------------------
// Main: single CTA, 512 threads, 16 rows/thread as 8 s16x2 regs (g) plus
// m = relu(g). Exact accept rule:  D = sum_r c'*(relu(g+c') + relu(g)) > 0.
// Per pair: vadd2 + vmaxs2 + (1/2) PRMT + 2x DP2A  = 2.5 alu + 2 fma ops.
// Prefetch depth 2 through a 3-slot buffer (unroll 3 -> no rotation moves).
// One __syncthreads per step (double-buffered warp partials).
// ---------------------------------------------------------------------------
__global__ __launch_bounds__(512, 1)
void k_main(const float* __restrict__ state, const int* __restrict__ perm,
            float* __restrict__ out) {
    __shared__ float s_state[N_BITS];
    __shared__ int   s_perm[N_BITS];
    __shared__ int   s_wpart[2][32];

    int t = threadIdx.x;
    for (int k = t; k < N_BITS; k += 512) {
        s_state[k] = state[k];
        s_perm[k]  = perm[k];
    }
    if (t < 32) { s_wpart[0][t] = 0; s_wpart[1][t] = 0; }

    const short* __restrict__ Cb = g_C + t * 16;   // this thread's 16-row slice

    int g2[8], m2[8];
    #pragma unroll
    for (int k = 0; k < 8; k++) {
        int a = g_g0[t * 16 + 2 * k];
        int b = g_g0[t * 16 + 2 * k + 1];
        g2[k] = (a & 0xFFFF) | (b << 16);
        m2[k] = (max(a, 0) & 0xFFFF) | (max(b, 0) << 16);
    }
    __syncthreads();

    uint4 bufA[3], bufB[3];
    {
        int i0 = s_perm[0], i1 = s_perm[1];
        bufA[0] = __ldg(reinterpret_cast<const uint4*>(Cb + (size_t)i0 * N_PAT));
        bufB[0] = __ldg(reinterpret_cast<const uint4*>(Cb + (size_t)i0 * N_PAT + 8));
        bufA[1] = __ldg(reinterpret_cast<const uint4*>(Cb + (size_t)i1 * N_PAT));
        bufB[1] = __ldg(reinterpret_cast<const uint4*>(Cb + (size_t)i1 * N_PAT + 8));
    }

    #pragma unroll 3
    for (int s = 0; s < N_BITS; s++) {
        // prefetch column for step s+2 (clamped; dup loads at the end are harmless)
        int ipf = s_perm[(s + 2 < N_BITS) ? (s + 2) : (N_BITS - 1)];
        bufA[(s + 2) % 3] = __ldg(reinterpret_cast<const uint4*>(Cb + (size_t)ipf * N_PAT));
        bufB[(s + 2) % 3] = __ldg(reinterpret_cast<const uint4*>(Cb + (size_t)ipf * N_PAT + 8));

        uint4 cA = bufA[s % 3], cB = bufB[s % 3];

        int gn2[8], mn2[8];
        int D1 = 0, D2 = 0;

#define PAIR2(k, w0, w1) {                                   \
        int gnA = __vadd2(g2[k],     (int)(w0));             \
        int gnB = __vadd2(g2[k + 1], (int)(w1));             \
        gn2[k] = gnA; gn2[k + 1] = gnB;                      \
        int mnA = (int)__vmaxs2((unsigned)gnA, 0u);          \
        int mnB = (int)__vmaxs2((unsigned)gnB, 0u);          \
        mn2[k] = mnA; mn2[k + 1] = mnB;                      \
        int c4 = __byte_perm((int)(w0), (int)(w1), 0x6420);  \
        D1 = __dp2a_lo(mnA, c4, D1);                         \
        D1 = __dp2a_hi(mnB, c4, D1);                         \
        D2 = __dp2a_lo(m2[k], c4, D2);                       \
        D2 = __dp2a_hi(m2[k + 1], c4, D2); }

        PAIR2(0, cA.x, cA.y)
        PAIR2(2, cA.z, cA.w)
        PAIR2(4, cB.x, cB.y)
        PAIR2(6, cB.z, cB.w)
#undef PAIR2

        int d  = D1 + D2;                                    // per-thread delta/?? exact
        int wr = __reduce_add_sync(0xffffffffu, d);          // warp partial
        if ((t & 31) == 0) s_wpart[s & 1][t >> 5] = wr;
        __syncthreads();
        int total = __reduce_add_sync(0xffffffffu, s_wpart[s & 1][t & 31]);

        if (total > 0) {   // energy strictly decreases -> accept flip
            #pragma unroll
            for (int k = 0; k < 8; k++) { g2[k] = gn2[k]; m2[k] = mn2[k]; }
            if (t == 0) { int ip = s_perm[s]; out[ip] = -s_state[ip]; }
        }
    }
}

// ---------------------------------------------------------------------------
extern "C" void kernel_launch(void* const* d_in, const int* in_sizes, int n_in,
                              void* d_out, int out_size) {
    const float* W     = (const float*)d_in[0];
    const float* state = (const float*)d_in[1];
    const int*   perm  = (const int*)d_in[2];
    float*       out   = (float*)d_out;

    dim3 b1(32, 8), g1(N_BITS / 32, N_PAT / 128);
    k_buildU<<<g1, b1>>>(W, state);
    k_h0t<<<N_BITS / 256, 256>>>(state, out);
    k_main<<<1, 512>>>(state, perm, out);
}